// round 1
// baseline (speedup 1.0000x reference)
#include <cuda_runtime.h>
#include <math.h>

// ---------------- problem constants ----------------
#define D_      768
#define B_      32
#define N_      1024
#define I_      64
#define S_      4
#define RPB     (I_ * S_)        // 256 rows per batch item
#define R_      (B_ * RPB)       // 8192 total slot rows
#define D2_     (2 * D_)         // 1536

// ---------------- scratch (device globals; no allocs allowed) ----------------
__device__ __align__(16) float g_k[(size_t)B_ * N_ * D_];       // 100.7 MB
__device__ __align__(16) float g_v[(size_t)B_ * N_ * D_];       // 100.7 MB
__device__ __align__(16) float g_qint[I_ * D_];
__device__ __align__(16) float g_slots[(size_t)R_ * D_];        // [B][I*S][D]
__device__ __align__(16) float g_qslot[(size_t)R_ * D_];
__device__ __align__(16) float g_logits[(size_t)R_ * N_];       // [B][I*S][N]
__device__ __align__(16) float g_upd[(size_t)R_ * D_];
__device__ __align__(16) float g_hln[(size_t)R_ * D_];
__device__ __align__(16) float g_hmid[(size_t)R_ * D2_];

// ---------------- block reductions (256 threads) ----------------
__device__ __forceinline__ float blk_sum(float v) {
    __shared__ float sh[8];
    int tid = threadIdx.x;
    #pragma unroll
    for (int o = 16; o > 0; o >>= 1) v += __shfl_down_sync(0xffffffffu, v, o);
    if ((tid & 31) == 0) sh[tid >> 5] = v;
    __syncthreads();
    if (tid == 0) {
        float t = sh[0];
        #pragma unroll
        for (int w = 1; w < 8; w++) t += sh[w];
        sh[0] = t;
    }
    __syncthreads();
    float r = sh[0];
    __syncthreads();
    return r;
}

__device__ __forceinline__ float blk_max(float v) {
    __shared__ float sh[8];
    int tid = threadIdx.x;
    #pragma unroll
    for (int o = 16; o > 0; o >>= 1) v = fmaxf(v, __shfl_down_sync(0xffffffffu, v, o));
    if ((tid & 31) == 0) sh[tid >> 5] = v;
    __syncthreads();
    if (tid == 0) {
        float t = sh[0];
        #pragma unroll
        for (int w = 1; w < 8; w++) t = fmaxf(t, sh[w]);
        sh[0] = t;
    }
    __syncthreads();
    float r = sh[0];
    __syncthreads();
    return r;
}

// ---------------- generic tiled SGEMM ----------------
// C[M,N] = op(A[M,K] x B) with epilogue MODE.
// TRANSB=true : B is [N,K] row-major (C = A·Bᵀ, both operands K-contiguous)
// TRANSB=false: B is [K,N] row-major (C = A·B)
// MODE: 0 plain | 1 +bias[n] | 2 +bias[n]+extra[intent(r)][n] | 3 *alpha
//       4 gelu(x+bias[n]) | 5 +bias[n]+extra[r][n] (residual)
// N must be a multiple of 128; K a multiple of 8; M arbitrary (guarded).
#define BM 128
#define BN 128
#define BK 8
#define TM 8
#define TN 8

template<bool TRANSB, int MODE>
__global__ __launch_bounds__(256)
void gemm_kernel(const float* __restrict__ A, const float* __restrict__ Bmat,
                 float* __restrict__ C, int M, int N, int K,
                 long sA, long sB, long sC,
                 const float* __restrict__ bias, const float* __restrict__ extra,
                 float alpha)
{
    __shared__ float As[BK][BM + 4];
    __shared__ float Bs[BK][BN + 4];

    A    += (long)blockIdx.z * sA;
    Bmat += (long)blockIdx.z * sB;
    C    += (long)blockIdx.z * sC;

    const int tid  = threadIdx.x;
    const int tx   = tid & 15;        // n direction
    const int ty   = tid >> 4;        // m direction
    const int row0 = blockIdx.y * BM;
    const int col0 = blockIdx.x * BN;

    // A/B (transposed) loader indices: float4 per thread
    const int la_m = tid >> 1;          // 0..127
    const int la_k = (tid & 1) * 4;     // 0 or 4
    // B (non-transposed) loader indices
    const int lb_k = tid >> 5;          // 0..7
    const int lb_n = (tid & 31) * 4;    // 0..124

    float acc[TM][TN];
    #pragma unroll
    for (int i = 0; i < TM; i++)
        #pragma unroll
        for (int j = 0; j < TN; j++) acc[i][j] = 0.0f;

    for (int k0 = 0; k0 < K; k0 += BK) {
        // --- load A tile (guarded on M) ---
        {
            int arow = row0 + la_m;
            float4 av = make_float4(0.f, 0.f, 0.f, 0.f);
            if (arow < M)
                av = *reinterpret_cast<const float4*>(A + (long)arow * K + k0 + la_k);
            As[la_k + 0][la_m] = av.x;
            As[la_k + 1][la_m] = av.y;
            As[la_k + 2][la_m] = av.z;
            As[la_k + 3][la_m] = av.w;
        }
        // --- load B tile ---
        if (TRANSB) {
            float4 bv = *reinterpret_cast<const float4*>(Bmat + (long)(col0 + la_m) * K + k0 + la_k);
            Bs[la_k + 0][la_m] = bv.x;
            Bs[la_k + 1][la_m] = bv.y;
            Bs[la_k + 2][la_m] = bv.z;
            Bs[la_k + 3][la_m] = bv.w;
        } else {
            float4 bv = *reinterpret_cast<const float4*>(Bmat + (long)(k0 + lb_k) * N + col0 + lb_n);
            *reinterpret_cast<float4*>(&Bs[lb_k][lb_n]) = bv;
        }
        __syncthreads();

        #pragma unroll
        for (int kk = 0; kk < BK; kk++) {
            float a_frag[TM], b_frag[TN];
            #pragma unroll
            for (int i = 0; i < TM; i++) a_frag[i] = As[kk][ty * TM + i];
            #pragma unroll
            for (int j = 0; j < TN; j++) b_frag[j] = Bs[kk][tx * TN + j];
            #pragma unroll
            for (int i = 0; i < TM; i++)
                #pragma unroll
                for (int j = 0; j < TN; j++)
                    acc[i][j] += a_frag[i] * b_frag[j];
        }
        __syncthreads();
    }

    // --- epilogue ---
    #pragma unroll
    for (int i = 0; i < TM; i++) {
        int r = row0 + ty * TM + i;
        if (r >= M) continue;
        #pragma unroll
        for (int j = 0; j < TN; j++) {
            int c = col0 + tx * TN + j;
            float v = acc[i][j];
            if (MODE == 1) {
                v += bias[c];
            } else if (MODE == 2) {
                v += bias[c] + extra[((r & (RPB - 1)) >> 2) * D_ + c];
            } else if (MODE == 3) {
                v *= alpha;
            } else if (MODE == 4) {
                v += bias[c];
                v = 0.5f * v * (1.0f + erff(v * 0.7071067811865476f));
            } else if (MODE == 5) {
                v += bias[c] + extra[(long)r * N + c];
            }
            C[(long)r * N + c] = v;
        }
    }
}

// ---------------- slot init: slots[b,i,s,:] = mu[s] + noise[i,b,s]*sigma[s] ----------------
__global__ void init_slots_kernel(const float* __restrict__ noise,
                                  const float* __restrict__ mu,
                                  const float* __restrict__ sg,
                                  float* __restrict__ slots)
{
    const long total = (long)R_ * D_;
    for (long idx = (long)blockIdx.x * blockDim.x + threadIdx.x; idx < total;
         idx += (long)gridDim.x * blockDim.x) {
        int  d  = (int)(idx % D_);
        long r  = idx / D_;                 // b*256 + i*4 + s
        int  s  = (int)(r & 3);
        int  ii = (int)((r >> 2) & 63);
        int  bb = (int)(r >> 8);
        long ni = (((long)ii * B_ + bb) * S_ + s) * D_ + d;
        slots[idx] = mu[s * D_ + d] + noise[ni] * sg[s * D_ + d];
    }
}

// ---------------- softmax over N_=1024, one block (256 thr) per row ----------------
__global__ __launch_bounds__(256)
void softmax_kernel(float* __restrict__ logits)
{
    float* p = logits + (long)blockIdx.x * N_;
    int tid = threadIdx.x;
    float x[4];
    float m = -1e30f;
    #pragma unroll
    for (int j = 0; j < 4; j++) { x[j] = p[tid + j * 256]; m = fmaxf(m, x[j]); }
    m = blk_max(m);
    float s = 0.f;
    #pragma unroll
    for (int j = 0; j < 4; j++) { x[j] = expf(x[j] - m); s += x[j]; }
    s = blk_sum(s);
    float inv = 1.0f / s;
    #pragma unroll
    for (int j = 0; j < 4; j++) p[tid + j * 256] = x[j] * inv;
}

// ---------------- fused: slots = LN1(slots+upd); hln = LN2(slots) ----------------
__global__ __launch_bounds__(256)
void ln_fused_kernel(float* __restrict__ slots, const float* __restrict__ upd,
                     const float* __restrict__ g1, const float* __restrict__ b1,
                     const float* __restrict__ g2, const float* __restrict__ b2,
                     float* __restrict__ hln)
{
    const long row = blockIdx.x;
    float*       sp = slots + row * D_;
    const float* up = upd   + row * D_;
    int tid = threadIdx.x;

    float x[3];
    float s = 0.f;
    #pragma unroll
    for (int j = 0; j < 3; j++) {
        int c = tid + j * 256;
        x[j] = sp[c] + up[c];
        s += x[j];
    }
    float mu = blk_sum(s) * (1.0f / D_);
    float vs = 0.f;
    #pragma unroll
    for (int j = 0; j < 3; j++) { x[j] -= mu; vs += x[j] * x[j]; }
    float rs = rsqrtf(blk_sum(vs) * (1.0f / D_) + 1e-5f);

    float y[3];
    float s2 = 0.f;
    #pragma unroll
    for (int j = 0; j < 3; j++) {
        int c = tid + j * 256;
        y[j] = x[j] * rs * g1[c] + b1[c];
        sp[c] = y[j];
        s2 += y[j];
    }
    float mu2 = blk_sum(s2) * (1.0f / D_);
    float vs2 = 0.f;
    #pragma unroll
    for (int j = 0; j < 3; j++) { float t = y[j] - mu2; vs2 += t * t; }
    float rs2 = rsqrtf(blk_sum(vs2) * (1.0f / D_) + 1e-5f);
    #pragma unroll
    for (int j = 0; j < 3; j++) {
        int c = tid + j * 256;
        hln[row * D_ + c] = (y[j] - mu2) * rs2 * g2[c] + b2[c];
    }
}

// ---------------- scoring: out[b,i] = sum_s <slot_n, q_n> ----------------
__global__ __launch_bounds__(256)
void score_kernel(const float* __restrict__ slots, const float* __restrict__ iq,
                  float* __restrict__ out)
{
    int i = blockIdx.x;
    int b = blockIdx.y;
    int tid = threadIdx.x;

    float q[3];
    float qq = 0.f;
    #pragma unroll
    for (int j = 0; j < 3; j++) {
        q[j] = iq[i * D_ + tid + j * 256];
        qq += q[j] * q[j];
    }
    qq = blk_sum(qq);
    float qn = fmaxf(sqrtf(qq), 1e-12f);

    float score = 0.f;
    for (int s = 0; s < S_; s++) {
        const float* sp = slots + (((long)(b * I_ + i) * S_) + s) * D_;
        float ss = 0.f, sq = 0.f;
        #pragma unroll
        for (int j = 0; j < 3; j++) {
            float v = sp[tid + j * 256];
            ss += v * v;
            sq += v * q[j];
        }
        ss = blk_sum(ss);
        sq = blk_sum(sq);
        score += sq / (fmaxf(sqrtf(ss), 1e-12f) * qn);
    }
    if (tid == 0) out[(long)b * I_ + i] = score;  // TEMPERATURE = 1
}

// ---------------- host orchestration ----------------
extern "C" void kernel_launch(void* const* d_in, const int* in_sizes, int n_in,
                              void* d_out, int out_size)
{
    const float* tokens   = (const float*)d_in[0];
    const float* iq       = (const float*)d_in[1];
    const float* noise    = (const float*)d_in[2];
    const float* slot_mu  = (const float*)d_in[3];
    const float* slot_sg  = (const float*)d_in[4];
    const float* Wq_slot  = (const float*)d_in[5];
    const float* bq_slot  = (const float*)d_in[6];
    const float* Wq_int   = (const float*)d_in[7];
    const float* bq_int   = (const float*)d_in[8];
    const float* Wk       = (const float*)d_in[9];
    const float* bk       = (const float*)d_in[10];
    const float* Wv       = (const float*)d_in[11];
    const float* bv       = (const float*)d_in[12];
    const float* ln_s_g   = (const float*)d_in[13];
    const float* ln_s_b   = (const float*)d_in[14];
    const float* ln_m_g   = (const float*)d_in[15];
    const float* ln_m_b   = (const float*)d_in[16];
    const float* W1       = (const float*)d_in[17];
    const float* b1       = (const float*)d_in[18];
    const float* W2       = (const float*)d_in[19];
    const float* b2       = (const float*)d_in[20];
    float* out = (float*)d_out;

    float *k, *v, *qint, *slots, *qslot, *logits, *upd, *hln, *hmid;
    cudaGetSymbolAddress((void**)&k,      g_k);
    cudaGetSymbolAddress((void**)&v,      g_v);
    cudaGetSymbolAddress((void**)&qint,   g_qint);
    cudaGetSymbolAddress((void**)&slots,  g_slots);
    cudaGetSymbolAddress((void**)&qslot,  g_qslot);
    cudaGetSymbolAddress((void**)&logits, g_logits);
    cudaGetSymbolAddress((void**)&upd,    g_upd);
    cudaGetSymbolAddress((void**)&hln,    g_hln);
    cudaGetSymbolAddress((void**)&hmid,   g_hmid);

    const float scale = 0.036084391824351615f;  // 1/sqrt(768)
    const int BNtok = B_ * N_;                  // 32768

    // K/V projections: tokens[32768,768] x W[768,768]^T + bias
    gemm_kernel<true, 1><<<dim3(D_ / BN, BNtok / BM, 1), 256>>>(
        tokens, Wk, k, BNtok, D_, D_, 0, 0, 0, bk, nullptr, 1.f);
    gemm_kernel<true, 1><<<dim3(D_ / BN, BNtok / BM, 1), 256>>>(
        tokens, Wv, v, BNtok, D_, D_, 0, 0, 0, bv, nullptr, 1.f);

    // q_intent = iq x Wq_int^T + bq_int  (M=64, guarded)
    gemm_kernel<true, 1><<<dim3(D_ / BN, 1, 1), 256>>>(
        iq, Wq_int, qint, I_, D_, D_, 0, 0, 0, bq_int, nullptr, 1.f);

    // slots init
    init_slots_kernel<<<2048, 256>>>(noise, slot_mu, slot_sg, slots);

    for (int it = 0; it < 3; it++) {
        // q_slot = slots x Wq_slot^T + bq_slot + q_intent[i]
        gemm_kernel<true, 2><<<dim3(D_ / BN, R_ / BM, 1), 256>>>(
            slots, Wq_slot, qslot, R_, D_, D_, 0, 0, 0, bq_slot, qint, 1.f);

        // logits[b] = q_slot[b] x k[b]^T * scale   (batched over b)
        gemm_kernel<true, 3><<<dim3(N_ / BN, RPB / BM, B_), 256>>>(
            qslot, k, logits, RPB, N_, D_,
            (long)RPB * D_, (long)N_ * D_, (long)RPB * N_, nullptr, nullptr, scale);

        softmax_kernel<<<R_, 256>>>(logits);

        // updates[b] = attn[b] x v[b]
        gemm_kernel<false, 0><<<dim3(D_ / BN, RPB / BM, B_), 256>>>(
            logits, v, upd, RPB, D_, N_,
            (long)RPB * N_, (long)N_ * D_, (long)RPB * D_, nullptr, nullptr, 1.f);

        // slots = LN1(slots + upd); hln = LN2(slots)
        ln_fused_kernel<<<R_, 256>>>(slots, upd, ln_s_g, ln_s_b, ln_m_g, ln_m_b, hln);

        // hmid = gelu(hln x W1^T + b1)
        gemm_kernel<true, 4><<<dim3(D2_ / BN, R_ / BM, 1), 256>>>(
            hln, W1, hmid, R_, D2_, D_, 0, 0, 0, b1, nullptr, 1.f);

        // slots = slots + hmid x W2^T + b2
        gemm_kernel<true, 5><<<dim3(D_ / BN, R_ / BM, 1), 256>>>(
            hmid, W2, slots, R_, D_, D2_, 0, 0, 0, b2, slots, 1.f);
    }

    score_kernel<<<dim3(I_, B_), 256>>>(slots, iq, out);
}

// round 2
// speedup vs baseline: 2.5041x; 2.5041x over previous
#include <cuda_runtime.h>
#include <cuda_bf16.h>
#include <math.h>
#include <stdint.h>

// ---------------- problem constants ----------------
#define D_      768
#define B_      32
#define N_      1024
#define I_      64
#define S_      4
#define RPB     (I_ * S_)        // 256 rows per batch item
#define R_      (B_ * RPB)       // 8192 total slot rows
#define D2_     (2 * D_)         // 1536

// ---------------- scratch (device globals; no allocs allowed) ----------------
__device__ __align__(16) float g_k[(size_t)B_ * N_ * D_];       // [B][N][D]
__device__ __align__(16) float g_vT[(size_t)B_ * D_ * N_];      // [B][D][N]
__device__ __align__(16) float g_qint[I_ * D_];
__device__ __align__(16) float g_slots[(size_t)R_ * D_];        // [B][I*S][D]
__device__ __align__(16) float g_qslot[(size_t)R_ * D_];
__device__ __align__(16) float g_logits[(size_t)R_ * N_];       // [B][I*S][N]
__device__ __align__(16) float g_upd[(size_t)R_ * D_];
__device__ __align__(16) float g_hln[(size_t)R_ * D_];
__device__ __align__(16) float g_hmid[(size_t)R_ * D2_];

// ---------------- block reductions (256 threads) ----------------
__device__ __forceinline__ float blk_sum(float v) {
    __shared__ float sh[8];
    int tid = threadIdx.x;
    #pragma unroll
    for (int o = 16; o > 0; o >>= 1) v += __shfl_down_sync(0xffffffffu, v, o);
    if ((tid & 31) == 0) sh[tid >> 5] = v;
    __syncthreads();
    if (tid == 0) {
        float t = sh[0];
        #pragma unroll
        for (int w = 1; w < 8; w++) t += sh[w];
        sh[0] = t;
    }
    __syncthreads();
    float r = sh[0];
    __syncthreads();
    return r;
}

__device__ __forceinline__ float blk_max(float v) {
    __shared__ float sh[8];
    int tid = threadIdx.x;
    #pragma unroll
    for (int o = 16; o > 0; o >>= 1) v = fmaxf(v, __shfl_down_sync(0xffffffffu, v, o));
    if ((tid & 31) == 0) sh[tid >> 5] = v;
    __syncthreads();
    if (tid == 0) {
        float t = sh[0];
        #pragma unroll
        for (int w = 1; w < 8; w++) t = fmaxf(t, sh[w]);
        sh[0] = t;
    }
    __syncthreads();
    float r = sh[0];
    __syncthreads();
    return r;
}

// ---------------- bf16x3 tensor-core GEMM ----------------
// C[M,N] = op(A[M,K] x B[N,K]^T)   (both operands K-contiguous, row-major)
// Split each fp32 operand into bf16 hi + lo; accumulate Ah*Bh + Ah*Bl + Al*Bh
// in fp32 via mma.sync.m16n8k16. Error ~2^-16 per operand => ~1e-5 overall.
//
// MODE: 0 plain | 1 +bias[col] | 2 +bias[col]+qint[intent(row)][col] | 3 *alpha
//       4 gelu(x+bias[col]) | 5 +bias[col]+extra[row*N+col] | 6 +bias[row]
// N multiple of 128, K multiple of 32; M arbitrary (guarded).
#define BM 128
#define BN 128
#define BKK 32
#define SPAD 8                   // row stride = 40 bf16 = 20 words (conflict-free)

__device__ __forceinline__ void mma16816(float* c, const uint32_t* a, const uint32_t* b) {
    asm volatile(
        "mma.sync.aligned.m16n8k16.row.col.f32.bf16.bf16.f32 "
        "{%0,%1,%2,%3}, {%4,%5,%6,%7}, {%8,%9}, {%0,%1,%2,%3};"
        : "+f"(c[0]), "+f"(c[1]), "+f"(c[2]), "+f"(c[3])
        : "r"(a[0]), "r"(a[1]), "r"(a[2]), "r"(a[3]), "r"(b[0]), "r"(b[1]));
}

__device__ __forceinline__ uint32_t pack2(__nv_bfloat16 x, __nv_bfloat16 y) {
    __nv_bfloat162 t = __nv_bfloat162(x, y);
    return *reinterpret_cast<uint32_t*>(&t);
}

template<int MODE>
__global__ __launch_bounds__(256, 2)
void gemm_kernel(const float* __restrict__ A, const float* __restrict__ Bmat,
                 float* __restrict__ C, int M, int N, int K,
                 long sA, long sB, long sC,
                 const float* __restrict__ bias, const float* __restrict__ extra,
                 float alpha)
{
    __shared__ __nv_bfloat16 Ahi[BM][BKK + SPAD];
    __shared__ __nv_bfloat16 Alo[BM][BKK + SPAD];
    __shared__ __nv_bfloat16 Bhi[BN][BKK + SPAD];
    __shared__ __nv_bfloat16 Blo[BN][BKK + SPAD];

    A    += (long)blockIdx.z * sA;
    Bmat += (long)blockIdx.z * sB;
    C    += (long)blockIdx.z * sC;

    const int tid  = threadIdx.x;
    const int warp = tid >> 5;
    const int lane = tid & 31;
    const int gr   = lane >> 2;       // 0..7
    const int qp   = lane & 3;        // 0..3
    const int wm   = warp >> 2;       // 0..1  -> m offset wm*64
    const int wn   = warp & 3;        // 0..3  -> n offset wn*32
    const int row0 = blockIdx.y * BM;
    const int col0 = blockIdx.x * BN;

    // loaders: each thread one float4 per 32 rows
    const int lrow = tid >> 3;        // 0..31
    const int lc4  = (tid & 7) * 4;   // 0..28 step 4

    float acc[4][4][4];
    #pragma unroll
    for (int i = 0; i < 4; i++)
        #pragma unroll
        for (int j = 0; j < 4; j++)
            #pragma unroll
            for (int q = 0; q < 4; q++) acc[i][j][q] = 0.0f;

    for (int k0 = 0; k0 < K; k0 += BKK) {
        // ---- global -> smem (convert fp32 -> bf16 hi/lo) ----
        #pragma unroll
        for (int p = 0; p < 4; p++) {
            int r = p * 32 + lrow;
            // A tile (guard M)
            float4 av = make_float4(0.f, 0.f, 0.f, 0.f);
            if (row0 + r < M)
                av = *reinterpret_cast<const float4*>(A + (long)(row0 + r) * K + k0 + lc4);
            {
                __nv_bfloat16 h0 = __float2bfloat16_rn(av.x);
                __nv_bfloat16 h1 = __float2bfloat16_rn(av.y);
                __nv_bfloat16 h2 = __float2bfloat16_rn(av.z);
                __nv_bfloat16 h3 = __float2bfloat16_rn(av.w);
                __nv_bfloat16 l0 = __float2bfloat16_rn(av.x - __bfloat162float(h0));
                __nv_bfloat16 l1 = __float2bfloat16_rn(av.y - __bfloat162float(h1));
                __nv_bfloat16 l2 = __float2bfloat16_rn(av.z - __bfloat162float(h2));
                __nv_bfloat16 l3 = __float2bfloat16_rn(av.w - __bfloat162float(h3));
                *reinterpret_cast<uint32_t*>(&Ahi[r][lc4])     = pack2(h0, h1);
                *reinterpret_cast<uint32_t*>(&Ahi[r][lc4 + 2]) = pack2(h2, h3);
                *reinterpret_cast<uint32_t*>(&Alo[r][lc4])     = pack2(l0, l1);
                *reinterpret_cast<uint32_t*>(&Alo[r][lc4 + 2]) = pack2(l2, l3);
            }
            // B tile (N multiple of 128, no guard)
            float4 bv = *reinterpret_cast<const float4*>(Bmat + (long)(col0 + r) * K + k0 + lc4);
            {
                __nv_bfloat16 h0 = __float2bfloat16_rn(bv.x);
                __nv_bfloat16 h1 = __float2bfloat16_rn(bv.y);
                __nv_bfloat16 h2 = __float2bfloat16_rn(bv.z);
                __nv_bfloat16 h3 = __float2bfloat16_rn(bv.w);
                __nv_bfloat16 l0 = __float2bfloat16_rn(bv.x - __bfloat162float(h0));
                __nv_bfloat16 l1 = __float2bfloat16_rn(bv.y - __bfloat162float(h1));
                __nv_bfloat16 l2 = __float2bfloat16_rn(bv.z - __bfloat162float(h2));
                __nv_bfloat16 l3 = __float2bfloat16_rn(bv.w - __bfloat162float(h3));
                *reinterpret_cast<uint32_t*>(&Bhi[r][lc4])     = pack2(h0, h1);
                *reinterpret_cast<uint32_t*>(&Bhi[r][lc4 + 2]) = pack2(h2, h3);
                *reinterpret_cast<uint32_t*>(&Blo[r][lc4])     = pack2(l0, l1);
                *reinterpret_cast<uint32_t*>(&Blo[r][lc4 + 2]) = pack2(l2, l3);
            }
        }
        __syncthreads();

        // ---- compute: 2 k16 steps ----
        #pragma unroll
        for (int ks = 0; ks < 2; ks++) {
            const int kb = ks * 16;
            const int c0 = kb + 2 * qp;
            const int c2 = c0 + 8;

            // B fragments (kept live across im loop)
            uint32_t Bh[4][2], Bl[4][2];
            #pragma unroll
            for (int jn = 0; jn < 4; jn++) {
                int rb = wn * 32 + jn * 8 + gr;
                Bh[jn][0] = *reinterpret_cast<const uint32_t*>(&Bhi[rb][c0]);
                Bh[jn][1] = *reinterpret_cast<const uint32_t*>(&Bhi[rb][c2]);
                Bl[jn][0] = *reinterpret_cast<const uint32_t*>(&Blo[rb][c0]);
                Bl[jn][1] = *reinterpret_cast<const uint32_t*>(&Blo[rb][c2]);
            }
            #pragma unroll
            for (int im = 0; im < 4; im++) {
                int r0 = wm * 64 + im * 16 + gr;
                uint32_t Ah[4], Al[4];
                Ah[0] = *reinterpret_cast<const uint32_t*>(&Ahi[r0][c0]);
                Ah[1] = *reinterpret_cast<const uint32_t*>(&Ahi[r0 + 8][c0]);
                Ah[2] = *reinterpret_cast<const uint32_t*>(&Ahi[r0][c2]);
                Ah[3] = *reinterpret_cast<const uint32_t*>(&Ahi[r0 + 8][c2]);
                Al[0] = *reinterpret_cast<const uint32_t*>(&Alo[r0][c0]);
                Al[1] = *reinterpret_cast<const uint32_t*>(&Alo[r0 + 8][c0]);
                Al[2] = *reinterpret_cast<const uint32_t*>(&Alo[r0][c2]);
                Al[3] = *reinterpret_cast<const uint32_t*>(&Alo[r0 + 8][c2]);
                #pragma unroll
                for (int jn = 0; jn < 4; jn++) {
                    mma16816(acc[im][jn], Ah, Bh[jn]);
                    mma16816(acc[im][jn], Ah, Bl[jn]);
                    mma16816(acc[im][jn], Al, Bh[jn]);
                }
            }
        }
        __syncthreads();
    }

    // ---- epilogue ----
    #pragma unroll
    for (int im = 0; im < 4; im++) {
        #pragma unroll
        for (int half = 0; half < 2; half++) {
            int r = row0 + wm * 64 + im * 16 + gr + half * 8;
            if (r >= M) continue;
            #pragma unroll
            for (int jn = 0; jn < 4; jn++) {
                int c = col0 + wn * 32 + jn * 8 + 2 * qp;
                float v0 = acc[im][jn][half * 2 + 0];
                float v1 = acc[im][jn][half * 2 + 1];
                if (MODE == 1) {
                    v0 += bias[c]; v1 += bias[c + 1];
                } else if (MODE == 2) {
                    const float* e = extra + ((r & (RPB - 1)) >> 2) * D_;
                    v0 += bias[c] + e[c]; v1 += bias[c + 1] + e[c + 1];
                } else if (MODE == 3) {
                    v0 *= alpha; v1 *= alpha;
                } else if (MODE == 4) {
                    v0 += bias[c]; v1 += bias[c + 1];
                    v0 = 0.5f * v0 * (1.0f + erff(v0 * 0.7071067811865476f));
                    v1 = 0.5f * v1 * (1.0f + erff(v1 * 0.7071067811865476f));
                } else if (MODE == 5) {
                    const float* e = extra + (long)r * N;
                    v0 += bias[c] + e[c]; v1 += bias[c + 1] + e[c + 1];
                } else if (MODE == 6) {
                    float br = bias[r - (int)(row0 - blockIdx.y * BM)];  // r is global row; bias by row
                    // (blockIdx.z batching offsets C only; row index r in [0,M))
                    br = bias[r];
                    v0 += br; v1 += br;
                }
                float2 o = make_float2(v0, v1);
                *reinterpret_cast<float2*>(C + (long)r * N + c) = o;
            }
        }
    }
}

// ---------------- slot init ----------------
__global__ void init_slots_kernel(const float* __restrict__ noise,
                                  const float* __restrict__ mu,
                                  const float* __restrict__ sg,
                                  float* __restrict__ slots)
{
    const long total = (long)R_ * D_;
    for (long idx = (long)blockIdx.x * blockDim.x + threadIdx.x; idx < total;
         idx += (long)gridDim.x * blockDim.x) {
        int  d  = (int)(idx % D_);
        long r  = idx / D_;
        int  s  = (int)(r & 3);
        int  ii = (int)((r >> 2) & 63);
        int  bb = (int)(r >> 8);
        long ni = (((long)ii * B_ + bb) * S_ + s) * D_ + d;
        slots[idx] = mu[s * D_ + d] + noise[ni] * sg[s * D_ + d];
    }
}

// ---------------- softmax over N_=1024 ----------------
__global__ __launch_bounds__(256)
void softmax_kernel(float* __restrict__ logits)
{
    float* p = logits + (long)blockIdx.x * N_;
    int tid = threadIdx.x;
    float x[4];
    float m = -1e30f;
    #pragma unroll
    for (int j = 0; j < 4; j++) { x[j] = p[tid + j * 256]; m = fmaxf(m, x[j]); }
    m = blk_max(m);
    float s = 0.f;
    #pragma unroll
    for (int j = 0; j < 4; j++) { x[j] = expf(x[j] - m); s += x[j]; }
    s = blk_sum(s);
    float inv = 1.0f / s;
    #pragma unroll
    for (int j = 0; j < 4; j++) p[tid + j * 256] = x[j] * inv;
}

// ---------------- fused: slots = LN1(slots+upd); hln = LN2(slots) ----------------
__global__ __launch_bounds__(256)
void ln_fused_kernel(float* __restrict__ slots, const float* __restrict__ upd,
                     const float* __restrict__ g1, const float* __restrict__ b1,
                     const float* __restrict__ g2, const float* __restrict__ b2,
                     float* __restrict__ hln)
{
    const long row = blockIdx.x;
    float*       sp = slots + row * D_;
    const float* up = upd   + row * D_;
    int tid = threadIdx.x;

    float x[3];
    float s = 0.f;
    #pragma unroll
    for (int j = 0; j < 3; j++) {
        int c = tid + j * 256;
        x[j] = sp[c] + up[c];
        s += x[j];
    }
    float mu = blk_sum(s) * (1.0f / D_);
    float vs = 0.f;
    #pragma unroll
    for (int j = 0; j < 3; j++) { x[j] -= mu; vs += x[j] * x[j]; }
    float rs = rsqrtf(blk_sum(vs) * (1.0f / D_) + 1e-5f);

    float y[3];
    float s2 = 0.f;
    #pragma unroll
    for (int j = 0; j < 3; j++) {
        int c = tid + j * 256;
        y[j] = x[j] * rs * g1[c] + b1[c];
        sp[c] = y[j];
        s2 += y[j];
    }
    float mu2 = blk_sum(s2) * (1.0f / D_);
    float vs2 = 0.f;
    #pragma unroll
    for (int j = 0; j < 3; j++) { float t = y[j] - mu2; vs2 += t * t; }
    float rs2 = rsqrtf(blk_sum(vs2) * (1.0f / D_) + 1e-5f);
    #pragma unroll
    for (int j = 0; j < 3; j++) {
        int c = tid + j * 256;
        hln[row * D_ + c] = (y[j] - mu2) * rs2 * g2[c] + b2[c];
    }
}

// ---------------- scoring ----------------
__global__ __launch_bounds__(256)
void score_kernel(const float* __restrict__ slots, const float* __restrict__ iq,
                  float* __restrict__ out)
{
    int i = blockIdx.x;
    int b = blockIdx.y;
    int tid = threadIdx.x;

    float q[3];
    float qq = 0.f;
    #pragma unroll
    for (int j = 0; j < 3; j++) {
        q[j] = iq[i * D_ + tid + j * 256];
        qq += q[j] * q[j];
    }
    qq = blk_sum(qq);
    float qn = fmaxf(sqrtf(qq), 1e-12f);

    float score = 0.f;
    for (int s = 0; s < S_; s++) {
        const float* sp = slots + (((long)(b * I_ + i) * S_) + s) * D_;
        float ss = 0.f, sq = 0.f;
        #pragma unroll
        for (int j = 0; j < 3; j++) {
            float v = sp[tid + j * 256];
            ss += v * v;
            sq += v * q[j];
        }
        ss = blk_sum(ss);
        sq = blk_sum(sq);
        score += sq / (fmaxf(sqrtf(ss), 1e-12f) * qn);
    }
    if (tid == 0) out[(long)b * I_ + i] = score;
}

// ---------------- host orchestration ----------------
extern "C" void kernel_launch(void* const* d_in, const int* in_sizes, int n_in,
                              void* d_out, int out_size)
{
    const float* tokens   = (const float*)d_in[0];
    const float* iq       = (const float*)d_in[1];
    const float* noise    = (const float*)d_in[2];
    const float* slot_mu  = (const float*)d_in[3];
    const float* slot_sg  = (const float*)d_in[4];
    const float* Wq_slot  = (const float*)d_in[5];
    const float* bq_slot  = (const float*)d_in[6];
    const float* Wq_int   = (const float*)d_in[7];
    const float* bq_int   = (const float*)d_in[8];
    const float* Wk       = (const float*)d_in[9];
    const float* bk       = (const float*)d_in[10];
    const float* Wv       = (const float*)d_in[11];
    const float* bv       = (const float*)d_in[12];
    const float* ln_s_g   = (const float*)d_in[13];
    const float* ln_s_b   = (const float*)d_in[14];
    const float* ln_m_g   = (const float*)d_in[15];
    const float* ln_m_b   = (const float*)d_in[16];
    const float* W1       = (const float*)d_in[17];
    const float* b1       = (const float*)d_in[18];
    const float* W2       = (const float*)d_in[19];
    const float* b2       = (const float*)d_in[20];
    float* out = (float*)d_out;

    float *k, *vT, *qint, *slots, *qslot, *logits, *upd, *hln, *hmid;
    cudaGetSymbolAddress((void**)&k,      g_k);
    cudaGetSymbolAddress((void**)&vT,     g_vT);
    cudaGetSymbolAddress((void**)&qint,   g_qint);
    cudaGetSymbolAddress((void**)&slots,  g_slots);
    cudaGetSymbolAddress((void**)&qslot,  g_qslot);
    cudaGetSymbolAddress((void**)&logits, g_logits);
    cudaGetSymbolAddress((void**)&upd,    g_upd);
    cudaGetSymbolAddress((void**)&hln,    g_hln);
    cudaGetSymbolAddress((void**)&hmid,   g_hmid);

    const float scale = 0.036084391824351615f;  // 1/sqrt(768)
    const int BNtok = B_ * N_;                  // 32768

    // k = tokens x Wk^T + bk   [32768, 768]
    gemm_kernel<1><<<dim3(D_ / BN, BNtok / BM, 1), 256>>>(
        tokens, Wk, k, BNtok, D_, D_, 0, 0, 0, bk, nullptr, 1.f);

    // vT[b] = Wv x tokens[b]^T (+ bv by row)   [768, 1024] per b
    gemm_kernel<6><<<dim3(N_ / BN, D_ / BM, B_), 256>>>(
        Wv, tokens, vT, D_, N_, D_,
        0, (long)N_ * D_, (long)D_ * N_, bv, nullptr, 1.f);

    // q_intent = iq x Wq_int^T + bq_int   [64, 768]
    gemm_kernel<1><<<dim3(D_ / BN, 1, 1), 256>>>(
        iq, Wq_int, qint, I_, D_, D_, 0, 0, 0, bq_int, nullptr, 1.f);

    init_slots_kernel<<<2048, 256>>>(noise, slot_mu, slot_sg, slots);

    for (int it = 0; it < 3; it++) {
        // q_slot = slots x Wq_slot^T + bq_slot + q_intent[i]
        gemm_kernel<2><<<dim3(D_ / BN, R_ / BM, 1), 256>>>(
            slots, Wq_slot, qslot, R_, D_, D_, 0, 0, 0, bq_slot, qint, 1.f);

        // logits[b] = q_slot[b] x k[b]^T * scale
        gemm_kernel<3><<<dim3(N_ / BN, RPB / BM, B_), 256>>>(
            qslot, k, logits, RPB, N_, D_,
            (long)RPB * D_, (long)N_ * D_, (long)RPB * N_, nullptr, nullptr, scale);

        softmax_kernel<<<R_, 256>>>(logits);

        // updates[b] = attn[b] x vT[b]^T   (M=256, N=768, K=1024)
        gemm_kernel<0><<<dim3(D_ / BN, RPB / BM, B_), 256>>>(
            logits, vT, upd, RPB, D_, N_,
            (long)RPB * N_, (long)D_ * N_, (long)RPB * D_, nullptr, nullptr, 1.f);

        // slots = LN1(slots + upd); hln = LN2(slots)
        ln_fused_kernel<<<R_, 256>>>(slots, upd, ln_s_g, ln_s_b, ln_m_g, ln_m_b, hln);

        // hmid = gelu(hln x W1^T + b1)
        gemm_kernel<4><<<dim3(D2_ / BN, R_ / BM, 1), 256>>>(
            hln, W1, hmid, R_, D2_, D_, 0, 0, 0, b1, nullptr, 1.f);

        // slots = slots + hmid x W2^T + b2
        gemm_kernel<5><<<dim3(D_ / BN, R_ / BM, 1), 256>>>(
            hmid, W2, slots, R_, D_, D2_, 0, 0, 0, b2, slots, 1.f);
    }

    score_kernel<<<dim3(I_, B_), 256>>>(slots, iq, out);
}